// round 6
// baseline (speedup 1.0000x reference)
#include <cuda_runtime.h>
#include <cstdint>

// Fixed shapes from reference setup_inputs
#define BS   32
#define C    256
#define HW   4096          // 64*64
#define HID  32            // C / R
#define NPLANES (BS * C)   // 8192

#define GRID  512
#define BLOCK 256
#define NCHUNK 2
#define PLANES_PER_CHUNK (NPLANES / NCHUNK)       // 4096 (16 batches = 67MB, fits L2)
#define PLANES_PER_CTA   (PLANES_PER_CHUNK / GRID) // 8 -> one plane per warp

// Device-global scratch + barrier state (zero-initialized at module load).
// g_gen grows monotonically across graph replays (generation barrier);
// g_count self-resets to 0 inside each barrier -> replay-deterministic.
__device__ float             g_pooled[NPLANES];
__device__ unsigned          g_count = 0;
__device__ volatile unsigned g_gen   = 0;

__global__ __launch_bounds__(BLOCK, 4) void fused_persistent(
    const float* __restrict__ x,
    const float* __restrict__ w1, const float* __restrict__ b1,
    const float* __restrict__ w2, const float* __restrict__ b2,
    float* __restrict__ out)
{
    const int i = blockIdx.x;
    const int t = threadIdx.x;
    const int w = t >> 5;      // warp id (0..7)
    const int l = t & 31;      // lane

    __shared__ float  sp[C];
    __shared__ float  sh[HID];
    __shared__ float  sdelta[32];
    __shared__ float4 s_cf[8];

    // Barrier generation base: all threads read before any arrival can bump it.
    unsigned gen = g_gen;

#pragma unroll 1
    for (int c = 0; c < NCHUNK; ++c) {
        const int pbase = c * PLANES_PER_CHUNK + i * PLANES_PER_CTA;

        // ---------- Phase 1: pool. Warp w reduces plane pbase+w (16KB). ----------
        {
            const int p = pbase + w;
            const float4* __restrict__ x4 =
                reinterpret_cast<const float4*>(x) + (size_t)p * (HW / 4);
            float s = 0.f;
#pragma unroll
            for (int it = 0; it < 32; it += 8) {
                float4 v0 = x4[l + (it + 0) * 32];
                float4 v1 = x4[l + (it + 1) * 32];
                float4 v2 = x4[l + (it + 2) * 32];
                float4 v3 = x4[l + (it + 3) * 32];
                float4 v4 = x4[l + (it + 4) * 32];
                float4 v5 = x4[l + (it + 5) * 32];
                float4 v6 = x4[l + (it + 6) * 32];
                float4 v7 = x4[l + (it + 7) * 32];
                s += ((v0.x + v0.y) + (v0.z + v0.w)) + ((v1.x + v1.y) + (v1.z + v1.w))
                   + ((v2.x + v2.y) + (v2.z + v2.w)) + ((v3.x + v3.y) + (v3.z + v3.w))
                   + ((v4.x + v4.y) + (v4.z + v4.w)) + ((v5.x + v5.y) + (v5.z + v5.w))
                   + ((v6.x + v6.y) + (v6.z + v6.w)) + ((v7.x + v7.y) + (v7.z + v7.w));
            }
#pragma unroll
            for (int o = 16; o > 0; o >>= 1) s += __shfl_down_sync(0xffffffffu, s, o);
            if (l == 0) __stcg(&g_pooled[p], s * (1.0f / (float)HW));
        }

        // ---------- Grid barrier (all 512 CTAs resident in one wave). ----------
        __syncthreads();
        if (t == 0) {
            __threadfence();                       // release g_pooled writes
            unsigned old = atomicAdd(&g_count, 1u);
            if (old == GRID - 1) {
                g_count = 0u;
                __threadfence();
                g_gen = gen + 1u;                  // release next generation
            } else {
                while (g_gen != gen + 1u) __nanosleep(64);
            }
        }
        gen += 1u;
        __syncthreads();

        // ---------- Phase 2: per-CTA coefficients for its batch/channels. ----------
        const int b  = pbase >> 8;       // all 8 planes share one batch
        const int c0 = pbase & 255;      // first channel

        sp[t] = __ldcg(&g_pooled[b * C + t]);
        __syncthreads();

        if (t < HID) {
            float acc = b1[t];
            const float* __restrict__ w1r = w1 + t * C;
#pragma unroll 8
            for (int k = 0; k < C; ++k) acc = fmaf(sp[k], __ldg(&w1r[k]), acc);
            sh[t] = fmaxf(acc, 0.f);
        }
        __syncthreads();

        if (t < 32) {
            const int s  = t >> 2;       // channel slot 0..7
            const int o  = t & 3;        // output: 0=z00 1=z01 2=z10 3=z11
            const int cc = c0 + s;
            const int ro = (o < 2) ? (2 * cc + o) : (512 + 2 * cc + (o - 2));
            const float* __restrict__ w2r = w2 + (size_t)ro * HID;
            float z = b2[ro];
#pragma unroll
            for (int h = 0; h < HID; ++h) z = fmaf(sh[h], __ldg(&w2r[h]), z);
            sdelta[t] = tanhf(0.5f * z);             // == 2*sigmoid(z) - 1
        }
        __syncthreads();

        if (t < 8) {
            float4 cf;
            cf.x = 1.0f + sdelta[4 * t];             // a0 = 1 + 1.0*d(z00)
            cf.z = 1.0f + 0.5f * sdelta[4 * t + 1];  // q0 = 1 + 0.5*d(z01)
            cf.y =        sdelta[4 * t + 2];         // a1 = 0 + 1.0*d(z10)
            cf.w =        0.5f * sdelta[4 * t + 3];  // q1 = 0 + 0.5*d(z11)
            s_cf[t] = cf;
        }
        __syncthreads();

        // ---------- Phase 3: apply. Warp w, plane pbase+w, reads hit L2. ----------
        {
            const float4 cf = s_cf[w];
            const int p = pbase + w;
            const float4* __restrict__ x4 =
                reinterpret_cast<const float4*>(x) + (size_t)p * (HW / 4);
            float4* __restrict__ o4 =
                reinterpret_cast<float4*>(out) + (size_t)p * (HW / 4);

#pragma unroll
            for (int it = 0; it < 32; it += 8) {
                float4 v0 = __ldcs(&x4[l + (it + 0) * 32]);
                float4 v1 = __ldcs(&x4[l + (it + 1) * 32]);
                float4 v2 = __ldcs(&x4[l + (it + 2) * 32]);
                float4 v3 = __ldcs(&x4[l + (it + 3) * 32]);
                float4 v4 = __ldcs(&x4[l + (it + 4) * 32]);
                float4 v5 = __ldcs(&x4[l + (it + 5) * 32]);
                float4 v6 = __ldcs(&x4[l + (it + 6) * 32]);
                float4 v7 = __ldcs(&x4[l + (it + 7) * 32]);
#define APPLY_ST(v, idx)                                                      \
                {                                                             \
                    float4 r;                                                 \
                    r.x = fmaxf(fmaf(v.x, cf.x, cf.z), fmaf(v.x, cf.y, cf.w));\
                    r.y = fmaxf(fmaf(v.y, cf.x, cf.z), fmaf(v.y, cf.y, cf.w));\
                    r.z = fmaxf(fmaf(v.z, cf.x, cf.z), fmaf(v.z, cf.y, cf.w));\
                    r.w = fmaxf(fmaf(v.w, cf.x, cf.z), fmaf(v.w, cf.y, cf.w));\
                    __stcs(&o4[l + (idx) * 32], r);                           \
                }
                APPLY_ST(v0, it + 0) APPLY_ST(v1, it + 1)
                APPLY_ST(v2, it + 2) APPLY_ST(v3, it + 3)
                APPLY_ST(v4, it + 4) APPLY_ST(v5, it + 5)
                APPLY_ST(v6, it + 6) APPLY_ST(v7, it + 7)
#undef APPLY_ST
            }
        }
        // smem reuse in next chunk is ordered by the next grid barrier's
        // __syncthreads(); no extra sync needed here.
    }
}

extern "C" void kernel_launch(void* const* d_in, const int* in_sizes, int n_in,
                              void* d_out, int out_size) {
    const float* x  = (const float*)d_in[0];
    const float* w1 = (const float*)d_in[1];
    const float* b1 = (const float*)d_in[2];
    const float* w2 = (const float*)d_in[3];
    const float* b2 = (const float*)d_in[4];
    float* out = (float*)d_out;

    fused_persistent<<<GRID, BLOCK>>>(x, w1, b1, w2, b2, out);
}

// round 7
// speedup vs baseline: 1.0186x; 1.0186x over previous
#include <cuda_runtime.h>
#include <cstdint>

// Fixed shapes from reference setup_inputs
#define BS   32
#define C    256
#define HW   4096          // 64*64
#define HID  32            // C / R
#define NPLANES (BS * C)   // 8192

// Scratch in device globals (no allocations allowed)
__device__ float  g_pooled[NPLANES];   // [BS, C] plane means
__device__ float4 g_coef[NPLANES];     // (a0, a1, q0, q1) per (b,c)

// 128-bit write-through store: goes to DRAM without allocating an L2 line,
// so the output stream cannot evict x's tail from L2.
__device__ __forceinline__ void st_wt_v4(float4* p, float4 v) {
    asm volatile("st.global.wt.v4.f32 [%0], {%1, %2, %3, %4};"
                 :: "l"(p), "f"(v.x), "f"(v.y), "f"(v.z), "f"(v.w) : "memory");
}

// ---------------------------------------------------------------------------
// Kernel 1: mean pool over H*W. One CTA per plane, 256 threads, 4 float4
// front-batched loads. Default .ca reads: the LAST ~126MB of x remains
// resident in L2 at kernel end (LRU tail), which apply consumes first.
// ---------------------------------------------------------------------------
__global__ __launch_bounds__(256) void pool_kernel(const float* __restrict__ x) {
    const int p = blockIdx.x;                  // plane = b*C + c
    const int t = threadIdx.x;
    const float4* __restrict__ x4 = reinterpret_cast<const float4*>(x) + (size_t)p * (HW / 4);

    float4 v0 = x4[t];
    float4 v1 = x4[t + 256];
    float4 v2 = x4[t + 512];
    float4 v3 = x4[t + 768];

    float s = ((v0.x + v0.y) + (v0.z + v0.w))
            + ((v1.x + v1.y) + (v1.z + v1.w))
            + ((v2.x + v2.y) + (v2.z + v2.w))
            + ((v3.x + v3.y) + (v3.z + v3.w));

#pragma unroll
    for (int o = 16; o > 0; o >>= 1) s += __shfl_down_sync(0xffffffffu, s, o);

    __shared__ float ws[8];
    if ((t & 31) == 0) ws[t >> 5] = s;
    __syncthreads();
    if (t < 8) {
        float v = ws[t];
#pragma unroll
        for (int o = 4; o > 0; o >>= 1) v += __shfl_down_sync(0xffu, v, o);
        if (t == 0) g_pooled[p] = v * (1.0f / (float)HW);
    }
}

// ---------------------------------------------------------------------------
// Kernel 2: coefficients. One CTA per batch element (32 CTAs, 256 threads).
// ---------------------------------------------------------------------------
__global__ __launch_bounds__(256) void coef_kernel(const float* __restrict__ w1,
                                                   const float* __restrict__ b1,
                                                   const float* __restrict__ w2,
                                                   const float* __restrict__ b2) {
    const int b = blockIdx.x;
    const int t = threadIdx.x;

    __shared__ float sp[C];
    __shared__ float sh[HID];

    sp[t] = g_pooled[b * C + t];
    __syncthreads();

    if (t < HID) {
        float acc = b1[t];
        const float* __restrict__ w1r = w1 + t * C;
#pragma unroll 8
        for (int i = 0; i < C; ++i) acc = fmaf(sp[i], w1r[i], acc);
        sh[t] = fmaxf(acc, 0.f);
    }
    __syncthreads();

    const int cc = t;
    float z00 = b2[2 * cc];               // k=0 alpha
    float z01 = b2[2 * cc + 1];           // k=0 beta
    float z10 = b2[512 + 2 * cc];         // k=1 alpha
    float z11 = b2[512 + 2 * cc + 1];     // k=1 beta
    const float* __restrict__ r00 = w2 + (size_t)(2 * cc) * HID;
    const float* __restrict__ r01 = w2 + (size_t)(2 * cc + 1) * HID;
    const float* __restrict__ r10 = w2 + (size_t)(512 + 2 * cc) * HID;
    const float* __restrict__ r11 = w2 + (size_t)(512 + 2 * cc + 1) * HID;
#pragma unroll
    for (int h = 0; h < HID; ++h) {
        const float hv = sh[h];
        z00 = fmaf(hv, r00[h], z00);
        z01 = fmaf(hv, r01[h], z01);
        z10 = fmaf(hv, r10[h], z10);
        z11 = fmaf(hv, r11[h], z11);
    }
    float4 cf;
    cf.x = 1.0f + tanhf(0.5f * z00);          // a0 = 1 + 1.0*delta
    cf.y =        tanhf(0.5f * z10);          // a1 = 0 + 1.0*delta
    cf.z = 1.0f + 0.5f * tanhf(0.5f * z01);   // q0 = 1 + 0.5*delta
    cf.w =        0.5f * tanhf(0.5f * z11);   // q1 = 0 + 0.5*delta
    g_coef[b * C + cc] = cf;
}

// ---------------------------------------------------------------------------
// Kernel 3: out = max(x*a0+q0, x*a1+q1). Two planes per CTA, 8 front-batched
// float4 loads (MLP_p1=8). Reverse traversal consumes x's L2-resident tail
// first; __ldcs demotes x lines after their single use (frees room as the
// read front advances); st.global.wt writes bypass L2 allocation entirely so
// the out stream cannot evict x.
// ---------------------------------------------------------------------------
__global__ __launch_bounds__(256) void apply_kernel(const float* __restrict__ x,
                                                    float* __restrict__ out) {
    const int pp = (NPLANES / 2 - 1) - blockIdx.x;  // reverse pair index
    const int p0 = 2 * pp;
    const int p1 = 2 * pp + 1;
    const int t  = threadIdx.x;

    const float4 cf0 = __ldcg(&g_coef[p0]);
    const float4 cf1 = __ldcg(&g_coef[p1]);

    const float4* __restrict__ xa = reinterpret_cast<const float4*>(x) + (size_t)p0 * (HW / 4);
    const float4* __restrict__ xb = reinterpret_cast<const float4*>(x) + (size_t)p1 * (HW / 4);
    float4* __restrict__ oa = reinterpret_cast<float4*>(out) + (size_t)p0 * (HW / 4);
    float4* __restrict__ ob = reinterpret_cast<float4*>(out) + (size_t)p1 * (HW / 4);

    float4 a0v = __ldcs(&xa[t]);
    float4 a1v = __ldcs(&xa[t + 256]);
    float4 a2v = __ldcs(&xa[t + 512]);
    float4 a3v = __ldcs(&xa[t + 768]);
    float4 b0v = __ldcs(&xb[t]);
    float4 b1v = __ldcs(&xb[t + 256]);
    float4 b2v = __ldcs(&xb[t + 512]);
    float4 b3v = __ldcs(&xb[t + 768]);

#define APPLY4(r, v, cf)                                                     \
    r.x = fmaxf(fmaf(v.x, cf.x, cf.z), fmaf(v.x, cf.y, cf.w));               \
    r.y = fmaxf(fmaf(v.y, cf.x, cf.z), fmaf(v.y, cf.y, cf.w));               \
    r.z = fmaxf(fmaf(v.z, cf.x, cf.z), fmaf(v.z, cf.y, cf.w));               \
    r.w = fmaxf(fmaf(v.w, cf.x, cf.z), fmaf(v.w, cf.y, cf.w));

    float4 r;
    APPLY4(r, a0v, cf0) st_wt_v4(&oa[t],       r);
    APPLY4(r, a1v, cf0) st_wt_v4(&oa[t + 256], r);
    APPLY4(r, a2v, cf0) st_wt_v4(&oa[t + 512], r);
    APPLY4(r, a3v, cf0) st_wt_v4(&oa[t + 768], r);
    APPLY4(r, b0v, cf1) st_wt_v4(&ob[t],       r);
    APPLY4(r, b1v, cf1) st_wt_v4(&ob[t + 256], r);
    APPLY4(r, b2v, cf1) st_wt_v4(&ob[t + 512], r);
    APPLY4(r, b3v, cf1) st_wt_v4(&ob[t + 768], r);
#undef APPLY4
}

extern "C" void kernel_launch(void* const* d_in, const int* in_sizes, int n_in,
                              void* d_out, int out_size) {
    const float* x  = (const float*)d_in[0];
    const float* w1 = (const float*)d_in[1];
    const float* b1 = (const float*)d_in[2];
    const float* w2 = (const float*)d_in[3];
    const float* b2 = (const float*)d_in[4];
    float* out = (float*)d_out;

    pool_kernel<<<NPLANES, 256>>>(x);
    coef_kernel<<<BS, 256>>>(w1, b1, w2, b2);
    apply_kernel<<<NPLANES / 2, 256>>>(x, out);
}